// round 13
// baseline (speedup 1.0000x reference)
#include <cuda_runtime.h>
#include <math.h>

#define NN 8192
#define TT 32
#define FF 16
#define HH 128
#define NHEADS 4
#define EE 2048
#define NZ 65536
#define NH (NN*HH)

// ----------------- static device scratch (no allocs) -----------------
__device__ float g_scale1[512], g_shift1[512], g_sum1[512], g_sq1[512];
__device__ float g_scale2[HH], g_shift2[HH], g_sum2[HH], g_sq2[HH];
__device__ float g_WfragH[64 * 16 * 32 * 2];       // tf32 B-frags, h-part (256KB)
__device__ float g_WfragX[32 * 64 * 2 * 32 * 2];   // tf32 B-frags, x-part per t (1MB)
__device__ float g_bias[32 * 512];                 // combined per-t bias
__device__ float g_h0[NH];
__device__ float g_ctx[NN * TT * HH];
__device__ float g_q[NH];
__device__ float g_comb[NN * 2 * HH];
__device__ float g_xbn[NH];
__device__ float g_ef[EE * HH];
__device__ float g_xw[NN * 512];
__device__ float g_ew[EE * 512];
__device__ float g_xa[NN * NHEADS];
__device__ float g_ea[EE * NHEADS];
__device__ float g_alpha[NZ * NHEADS];
__device__ unsigned g_segmax[NN * NHEADS];
__device__ float g_segsum[NN * NHEADS];
__device__ float g_Dinv[NN];
__device__ float g_eout[EE * NHEADS * HH];
__device__ float g_x1[NH];
__device__ int g_cnt[NN], g_cursor[NN], g_rowptr[NN + 1], g_adj[NZ];

// ----------------- helpers -----------------
__device__ __forceinline__ unsigned fenc(float a) {
    unsigned u = __float_as_uint(a);
    return (u & 0x80000000u) ? ~u : (u | 0x80000000u);
}
__device__ __forceinline__ float fdec(unsigned u) {
    return (u & 0x80000000u) ? __uint_as_float(u & 0x7FFFFFFFu) : __uint_as_float(~u);
}
__device__ __forceinline__ float tf32r(float x) {
    unsigned u; asm("cvt.rna.tf32.f32 %0, %1;" : "=r"(u) : "f"(x));
    return __uint_as_float(u);
}
__device__ __forceinline__ float sigacc(float x) {
    return __fdividef(1.f, 1.f + __expf(-x));
}
__device__ __forceinline__ float tanhacc(float x) {
    return 1.f - __fdividef(2.f, __expf(2.f * x) + 1.f);
}
__device__ __forceinline__ void mma8(float* c, const unsigned* a, unsigned b0, unsigned b1) {
    asm volatile(
        "mma.sync.aligned.m16n8k8.row.col.f32.tf32.tf32.f32 "
        "{%0,%1,%2,%3}, {%4,%5,%6,%7}, {%8,%9}, {%0,%1,%2,%3};\n"
        : "+f"(c[0]), "+f"(c[1]), "+f"(c[2]), "+f"(c[3])
        : "r"(a[0]), "r"(a[1]), "r"(a[2]), "r"(a[3]), "r"(b0), "r"(b1));
}

// ----------------- batchnorm -----------------
__global__ void bn_stats(const float* __restrict__ x, int ncols, float* sum, float* sq) {
    __shared__ float ssum[32 * 33], ssq[32 * 33];
    int c = threadIdx.x & 31, rg = threadIdx.x >> 5;
    int col = blockIdx.x * 32 + c;
    float s = 0.f, q = 0.f;
    for (int r = rg; r < NN; r += 32) {
        float v = x[(size_t)r * ncols + col];
        s += v; q += v * v;
    }
    ssum[rg * 33 + c] = s; ssq[rg * 33 + c] = q;
    __syncthreads();
    if (threadIdx.x < 32) {
        float S = 0.f, Q = 0.f;
        for (int g = 0; g < 32; g++) { S += ssum[g * 33 + threadIdx.x]; Q += ssq[g * 33 + threadIdx.x]; }
        sum[blockIdx.x * 32 + threadIdx.x] = S;
        sq[blockIdx.x * 32 + threadIdx.x] = Q;
    }
}
__global__ void bn_finalize(const float* sum, const float* sq, const float* g,
                            const float* b, float* scale, float* shift, int ncols) {
    int c = blockIdx.x * blockDim.x + threadIdx.x;
    if (c >= ncols) return;
    float m = sum[c] * (1.f / NN);
    float v = sq[c] * (1.f / NN) - m * m;
    float sc = rsqrtf(v + 1e-5f) * g[c];
    scale[c] = sc; shift[c] = b[c] - m * sc;
}
__global__ void bn_apply(const float* __restrict__ x, const float* scale,
                         const float* shift, float* y, int* cnt) {
    int i = blockIdx.x * blockDim.x + threadIdx.x;
    if (i >= NH) return;
    int c = i & (HH - 1);
    y[i] = x[i] * scale[c] + shift[c];
    if (i < NN) cnt[i] = 0;
}

// ----------------- GRU prep: fragment-ready tf32 weights + biases -----------------
__global__ void prep_all(const float* __restrict__ Whh, const float* __restrict__ Wih,
                         const float* __restrict__ bih, const float* __restrict__ bhh) {
    int b = blockIdx.x, tid = threadIdx.x;
    if (b < 128) {                       // WfragH: [ntg 64][ks 16][lane 32][2]
        int idx = b * 256 + tid;
        int lane = idx & 31, ks = (idx >> 5) & 15, ntg = idx >> 9;
        int k = ks * 8 + (lane & 3), c = ntg * 8 + (lane >> 2);
        int j = c >> 2, p = c & 3;
        float b0 = 0.f, b1 = 0.f;
        if (p != 2) {
            int g = (p == 3) ? (256 + j) : (p * 128 + j);
            b0 = Whh[g * 128 + k]; b1 = Whh[g * 128 + k + 4];
        }
        g_WfragH[idx * 2] = tf32r(b0); g_WfragH[idx * 2 + 1] = tf32r(b1);
    } else if (b < 640) {                // WfragX: [t 32][ntg 64][ks2 2][lane 32][2]
        int idx = (b - 128) * 256 + tid;
        int lane = idx & 31, ks2 = (idx >> 5) & 1, ntg = (idx >> 6) & 63, t = idx >> 12;
        int f = ks2 * 8 + (lane & 3), c = ntg * 8 + (lane >> 2);
        int j = c >> 2, p = c & 3;
        float b0 = 0.f, b1 = 0.f;
        if (p != 3) {
            int g = p * 128 + j;
            b0 = Wih[g * 16 + f] * g_scale1[t * 16 + f];
            b1 = Wih[g * 16 + f + 4] * g_scale1[t * 16 + f + 4];
        }
        g_WfragX[idx * 2] = tf32r(b0); g_WfragX[idx * 2 + 1] = tf32r(b1);
    } else {                             // bias: [t 32][c 512]
        int idx = (b - 640) * 256 + tid;
        int c = idx & 511, t = idx >> 9;
        int j = c >> 2, p = c & 3;
        float v;
        if (p == 3) v = bhh[256 + j];
        else {
            int g = p * 128 + j;
            float sd = 0.f;
            for (int f = 0; f < 16; f++) sd += g_shift1[t * 16 + f] * Wih[g * 16 + f];
            v = bih[g] + sd + ((p < 2) ? bhh[g] : 0.f);
        }
        g_bias[t * 512 + c] = v;
    }
}

// ----------------- persistent tf32-mma GRU (512 threads, 16 warps) -----------------
#define GPAD 132
__global__ void __launch_bounds__(512)
gru_persist(const float* __restrict__ price) {
    __shared__ float sh[64 * GPAD];
    __shared__ float sx[64 * 20];
    __shared__ float sbias[512];
    int tid = threadIdx.x, lane = tid & 31, warp = tid >> 5;
    int gid = lane >> 2, q = lane & 3;
    int node0 = blockIdx.x * 64;

    for (int i = tid; i < 64 * GPAD; i += 512) sh[i] = 0.f;
    __syncthreads();

    const float2* __restrict__ WH = (const float2*)g_WfragH;

    for (int t = 0; t < TT; t++) {
        for (int i = tid; i < 1024; i += 512) {
            int nd = i >> 4, f = i & 15;
            sx[nd * 20 + f] = tf32r(price[(size_t)(node0 + nd) * 512 + t * 16 + f]);
        }
        if (tid < 512) sbias[tid] = g_bias[t * 512 + tid];
        __syncthreads();   // A

        const float2* __restrict__ WXt = (const float2*)g_WfragX + (size_t)t * 4096;

        float acc[4][4][4];
#pragma unroll
        for (int mt = 0; mt < 4; mt++)
#pragma unroll
            for (int nt = 0; nt < 4; nt++) {
                int cb = warp * 32 + nt * 8 + 2 * q;
                float2 bv = *(const float2*)&sbias[cb];
                acc[mt][nt][0] = bv.x; acc[mt][nt][1] = bv.y;
                acc[mt][nt][2] = bv.x; acc[mt][nt][3] = bv.y;
            }

        float2 bcur[4], bnxt[4];
#pragma unroll
        for (int nt = 0; nt < 4; nt++)
            bcur[nt] = WH[(((warp * 4 + nt) * 16) + 0) * 32 + lane];

        for (int ks = 0; ks < 18; ks++) {
            if (ks < 17) {
                int kn = ks + 1;
                if (kn < 16) {
#pragma unroll
                    for (int nt = 0; nt < 4; nt++)
                        bnxt[nt] = WH[(((warp * 4 + nt) * 16) + kn) * 32 + lane];
                } else {
                    int ks2 = kn - 16;
#pragma unroll
                    for (int nt = 0; nt < 4; nt++)
                        bnxt[nt] = WXt[(((warp * 4 + nt) * 2) + ks2) * 32 + lane];
                }
            }
            unsigned a[4][4];
            if (ks < 16) {
                int base = ks * 8 + q;
#pragma unroll
                for (int mt = 0; mt < 4; mt++) {
                    int r0 = mt * 16 + gid;
                    a[mt][0] = __float_as_uint(sh[r0 * GPAD + base]);
                    a[mt][1] = __float_as_uint(sh[(r0 + 8) * GPAD + base]);
                    a[mt][2] = __float_as_uint(sh[r0 * GPAD + base + 4]);
                    a[mt][3] = __float_as_uint(sh[(r0 + 8) * GPAD + base + 4]);
                }
            } else {
                int base = (ks - 16) * 8 + q;
#pragma unroll
                for (int mt = 0; mt < 4; mt++) {
                    int r0 = mt * 16 + gid;
                    a[mt][0] = __float_as_uint(sx[r0 * 20 + base]);
                    a[mt][1] = __float_as_uint(sx[(r0 + 8) * 20 + base]);
                    a[mt][2] = __float_as_uint(sx[r0 * 20 + base + 4]);
                    a[mt][3] = __float_as_uint(sx[(r0 + 8) * 20 + base + 4]);
                }
            }
#pragma unroll
            for (int nt = 0; nt < 4; nt++) {
                unsigned b0 = __float_as_uint(bcur[nt].x), b1 = __float_as_uint(bcur[nt].y);
#pragma unroll
                for (int mt = 0; mt < 4; mt++) mma8(acc[mt][nt], a[mt], b0, b1);
            }
#pragma unroll
            for (int nt = 0; nt < 4; nt++) bcur[nt] = bnxt[nt];
        }

        __syncthreads();   // B

#pragma unroll
        for (int mt = 0; mt < 4; mt++)
#pragma unroll
            for (int nt = 0; nt < 4; nt++) {
                float c0 = acc[mt][nt][0], c1 = acc[mt][nt][1];
                float c2 = acc[mt][nt][2], c3 = acc[mt][nt][3];
                float v0 = __shfl_xor_sync(0xffffffffu, c0, 1);
                float v1 = __shfl_xor_sync(0xffffffffu, c1, 1);
                float v2 = __shfl_xor_sync(0xffffffffu, c2, 1);
                float v3 = __shfl_xor_sync(0xffffffffu, c3, 1);
                int cb = warp * 32 + nt * 8 + 2 * q;
                int j = cb >> 2;
                float ra, za, nx, nh; int row;
                if ((q & 1) == 0) { row = mt * 16 + gid;     ra = c0; za = c1; nx = v0; nh = v1; }
                else              { row = mt * 16 + gid + 8; ra = v2; za = v3; nx = c2; nh = c3; }
                float r = sigacc(ra), z = sigacc(za);
                float n = tanhacc(nx + r * nh);
                float hold = sh[row * GPAD + j];
                sh[row * GPAD + j] = tf32r((1.f - z) * n + z * hold);
            }
        __syncthreads();   // C

        size_t cbase = (size_t)node0 * 4096 + (size_t)t * 128;
        for (int i = tid; i < 2048; i += 512) {
            int nd = i >> 5, jq = i & 31;
            float4 v = *(const float4*)&sh[nd * GPAD + jq * 4];
            *(float4*)&g_ctx[cbase + (size_t)nd * 4096 + jq * 4] = v;
            if (t == 31) *(float4*)&g_h0[(size_t)(node0 + nd) * 128 + jq * 4] = v;
        }
    }
}

// ----------------- tf32 3-mma split GEMM: C = act(A(M,K) @ B(Nc,K)^T) -----------------
// block 256 thr (8 warps: 4m x 2n), tile m128 x n64, K-chunk 16. fp32-accurate.
#define KP 20
__global__ void __launch_bounds__(256)
gemm_tf32(const float* __restrict__ A, const float* __restrict__ B,
          float* __restrict__ C, int M, int Nc, int K, int act) {
    __shared__ float Ah[128 * KP], Al[128 * KP], Bh[64 * KP], Bl[64 * KP];
    int tid = threadIdx.x, lane = tid & 31, warp = tid >> 5;
    int wm = warp & 3, wn = warp >> 2;
    int m0 = blockIdx.y * 128, n0 = blockIdx.x * 64;
    int gid = lane >> 2, q = lane & 3;
    float acc[2][4][4];
#pragma unroll
    for (int mt = 0; mt < 2; mt++)
#pragma unroll
        for (int nt = 0; nt < 4; nt++)
#pragma unroll
            for (int v = 0; v < 4; v++) acc[mt][nt][v] = 0.f;

    for (int k0 = 0; k0 < K; k0 += 16) {
        __syncthreads();
        // A tile: 128 rows x 16 k = 512 float4
        for (int i = tid; i < 512; i += 256) {
            int r = i >> 2, kq4 = i & 3;
            float4 v = *(const float4*)&A[(size_t)(m0 + r) * K + k0 + kq4 * 4];
            float h0 = tf32r(v.x), h1 = tf32r(v.y), h2 = tf32r(v.z), h3 = tf32r(v.w);
            int o = r * KP + kq4 * 4;
            Ah[o] = h0; Ah[o + 1] = h1; Ah[o + 2] = h2; Ah[o + 3] = h3;
            Al[o] = tf32r(v.x - h0); Al[o + 1] = tf32r(v.y - h1);
            Al[o + 2] = tf32r(v.z - h2); Al[o + 3] = tf32r(v.w - h3);
        }
        // B tile: 64 x 16 = 256 float4
        for (int i = tid; i < 256; i += 256) {
            int r = i >> 2, kq4 = i & 3;
            float4 v = *(const float4*)&B[(size_t)(n0 + r) * K + k0 + kq4 * 4];
            float h0 = tf32r(v.x), h1 = tf32r(v.y), h2 = tf32r(v.z), h3 = tf32r(v.w);
            int o = r * KP + kq4 * 4;
            Bh[o] = h0; Bh[o + 1] = h1; Bh[o + 2] = h2; Bh[o + 3] = h3;
            Bl[o] = tf32r(v.x - h0); Bl[o + 1] = tf32r(v.y - h1);
            Bl[o + 2] = tf32r(v.z - h2); Bl[o + 3] = tf32r(v.w - h3);
        }
        __syncthreads();
#pragma unroll
        for (int kk = 0; kk < 2; kk++) {
            int kb = kk * 8 + q;
            unsigned ah[2][4], al[2][4];
#pragma unroll
            for (int mt = 0; mt < 2; mt++) {
                int r0 = wm * 32 + mt * 16 + gid;
                ah[mt][0] = __float_as_uint(Ah[r0 * KP + kb]);
                ah[mt][1] = __float_as_uint(Ah[(r0 + 8) * KP + kb]);
                ah[mt][2] = __float_as_uint(Ah[r0 * KP + kb + 4]);
                ah[mt][3] = __float_as_uint(Ah[(r0 + 8) * KP + kb + 4]);
                al[mt][0] = __float_as_uint(Al[r0 * KP + kb]);
                al[mt][1] = __float_as_uint(Al[(r0 + 8) * KP + kb]);
                al[mt][2] = __float_as_uint(Al[r0 * KP + kb + 4]);
                al[mt][3] = __float_as_uint(Al[(r0 + 8) * KP + kb + 4]);
            }
#pragma unroll
            for (int nt = 0; nt < 4; nt++) {
                int c = wn * 32 + nt * 8 + gid;
                int kbb = kk * 8 + q;
                unsigned bh0 = __float_as_uint(Bh[c * KP + kbb]);
                unsigned bh1 = __float_as_uint(Bh[c * KP + kbb + 4]);
                unsigned bl0 = __float_as_uint(Bl[c * KP + kbb]);
                unsigned bl1 = __float_as_uint(Bl[c * KP + kbb + 4]);
#pragma unroll
                for (int mt = 0; mt < 2; mt++) {
                    mma8(acc[mt][nt], ah[mt], bh0, bh1);
                    mma8(acc[mt][nt], al[mt], bh0, bh1);
                    mma8(acc[mt][nt], ah[mt], bl0, bl1);
                }
            }
        }
    }
#pragma unroll
    for (int mt = 0; mt < 2; mt++)
#pragma unroll
        for (int nt = 0; nt < 4; nt++) {
            int row = m0 + wm * 32 + mt * 16 + gid;
            int col = n0 + wn * 32 + nt * 8 + 2 * q;
            float v0 = acc[mt][nt][0], v1 = acc[mt][nt][1];
            float v2 = acc[mt][nt][2], v3 = acc[mt][nt][3];
            if (act == 1) { v0 = tanhf(v0); v1 = tanhf(v1); v2 = tanhf(v2); v3 = tanhf(v3); }
            float2 p0 = {v0, v1}, p1 = {v2, v3};
            *(float2*)&C[(size_t)row * Nc + col] = p0;
            *(float2*)&C[(size_t)(row + 8) * Nc + col] = p1;
        }
}

// ----------------- temporal attention middle -----------------
__global__ void attn_mid(const float* __restrict__ ae, const float* __restrict__ ab) {
    __shared__ float sctx[32 * 129], sq[128], sw[32], sbt[32];
    int n = blockIdx.x, tid = threadIdx.x;
    sq[tid] = g_q[n * HH + tid];
    for (int idx = tid; idx < TT * HH; idx += 128) {
        int t = idx >> 7, k = idx & 127;
        sctx[t * 129 + k] = g_ctx[(size_t)n * (TT * HH) + idx];
    }
    __syncthreads();
    if (tid < 32) {
        float s = 0.f;
        for (int k = 0; k < 128; k++) s += sq[k] * sctx[tid * 129 + k];
        float m = s;
#pragma unroll
        for (int o = 16; o; o >>= 1) m = fmaxf(m, __shfl_xor_sync(0xffffffffu, m, o));
        float e = expf(s - m), su = e;
#pragma unroll
        for (int o = 16; o; o >>= 1) su += __shfl_xor_sync(0xffffffffu, su, o);
        sw[tid] = e / su;
        sbt[tid] = expf(-ab[n] * (float)(31 - tid));
    }
    __syncthreads();
    float aen = ae[n], acc = 0.f;
#pragma unroll 4
    for (int t = 0; t < TT; t++) {
        float mx = sw[t] * sctx[t * 129 + tid];
        acc += mx + fmaxf(aen * mx * sbt[t], 0.f);
    }
    g_comb[n * 256 + tid] = acc;
    g_comb[n * 256 + 128 + tid] = sq[tid];
}

// ----------------- CSR build (by src) -----------------
__global__ void count_src(const int* __restrict__ e0, int* cnt) {
    int i = blockIdx.x * blockDim.x + threadIdx.x;
    if (i < NZ) atomicAdd(&cnt[e0[i]], 1);
}
__global__ void scan_csr(const int* __restrict__ cnt, int* rowptr, float* Dinv, int* cursor) {
    __shared__ int s[1024];
    int tid = threadIdx.x, base = tid * 8, loc[8], sum = 0;
#pragma unroll
    for (int j = 0; j < 8; j++) { loc[j] = sum; sum += cnt[base + j]; }
    s[tid] = sum;
    __syncthreads();
    for (int off = 1; off < 1024; off <<= 1) {
        int v = (tid >= off) ? s[tid - off] : 0;
        __syncthreads();
        s[tid] += v;
        __syncthreads();
    }
    int excl = tid ? s[tid - 1] : 0;
#pragma unroll
    for (int j = 0; j < 8; j++) {
        rowptr[base + j] = excl + loc[j];
        int c = cnt[base + j];
        Dinv[base + j] = c ? 1.f / (float)c : 0.f;
        cursor[base + j] = 0;
    }
    if (tid == 1023) rowptr[NN] = s[1023];
}
__global__ void fill_csr(const int* __restrict__ e0, const int* __restrict__ rowptr,
                         int* cursor, int* adj, unsigned* segmax, float* segsum) {
    int i = blockIdx.x * blockDim.x + threadIdx.x;
    if (i >= NZ) return;
    if (i < NN * NHEADS) { segmax[i] = 0u; segsum[i] = 0.f; }
    int sg = e0[i];
    int p = atomicAdd(&cursor[sg], 1);
    adj[rowptr[sg] + p] = i;
}

// ----------------- hypergraph pieces -----------------
__global__ void efeat(const int* __restrict__ e0, const float* __restrict__ x, float* ef,
                      unsigned* segmax, float* segsum, int zeroseg) {
    int d = blockIdx.x, c = threadIdx.x;
    if (zeroseg) {
        int gid = d * 128 + c;
        if (gid < NN) { segmax[gid] = 0u; segsum[gid] = 0.f; }
    }
    float a = 0.f;
#pragma unroll 4
    for (int j = 0; j < 32; j++) a += x[e0[d + j * EE] * HH + c];
    ef[d * HH + c] = a;
}

__global__ void rowdot(const float* __restrict__ xw, const float* __restrict__ att,
                       int stride, int heads, float* __restrict__ out) {
    int r = blockIdx.x, h = threadIdx.x >> 5, lane = threadIdx.x & 31;
    const float* row = xw + (size_t)(r * heads + h) * HH;
    float s = 0.f;
#pragma unroll
    for (int m = 0; m < 4; m++) s += row[lane + 32 * m] * att[h * stride + lane + 32 * m];
#pragma unroll
    for (int o = 16; o; o >>= 1) s += __shfl_xor_sync(0xffffffffu, s, o);
    if (!lane) out[r * heads + h] = s;
}

__global__ void alpha_max(const int* __restrict__ e0, const int* __restrict__ e1,
                          const float* __restrict__ xa, const float* __restrict__ ea,
                          int heads) {
    int g = blockIdx.x * blockDim.x + threadIdx.x;
    if (g >= NZ * heads) return;
    int i = g / heads, h = g - i * heads;
    float a = xa[e0[i] * heads + h] + ea[e1[i] * heads + h];
    a = (a > 0.f) ? a : 0.2f * a;
    g_alpha[g] = a;
    atomicMax(&g_segmax[e0[i] * heads + h], fenc(a));
}
__global__ void alpha_exp(const int* __restrict__ e0, int heads) {
    int g = blockIdx.x * blockDim.x + threadIdx.x;
    if (g >= NZ * heads) return;
    int i = g / heads, h = g - i * heads;
    float ex = expf(g_alpha[g] - fdec(g_segmax[e0[i] * heads + h]));
    g_alpha[g] = ex;
    atomicAdd(&g_segsum[e0[i] * heads + h], ex);
}

template <int HT>
__global__ void eout_gather(const int* __restrict__ e0, const float* __restrict__ xw) {
    int d = blockIdx.x, c = threadIdx.x;
    float acc[HT];
#pragma unroll
    for (int h = 0; h < HT; h++) acc[h] = 0.f;
    for (int j = 0; j < 32; j++) {
        int i = d + j * EE, s = e0[i];
#pragma unroll
        for (int h = 0; h < HT; h++) {
            float an = g_alpha[i * HT + h] / (g_segsum[s * HT + h] + 1e-16f);
            acc[h] += an * xw[(size_t)(s * HT + h) * HH + c];
        }
    }
#pragma unroll
    for (int h = 0; h < HT; h++)
        g_eout[(size_t)(d * HT + h) * HH + c] = acc[h] * (1.f / 32.f);
}

template <int HT>
__global__ void node_out(const int* __restrict__ e1, const float* __restrict__ bias,
                         float* __restrict__ out) {
    int s = blockIdx.x, c = threadIdx.x;
    int b = g_rowptr[s], e = g_rowptr[s + 1];
    float ssv[HT];
#pragma unroll
    for (int h = 0; h < HT; h++) ssv[h] = g_segsum[s * HT + h] + 1e-16f;
    float a[HT];
#pragma unroll
    for (int h = 0; h < HT; h++) a[h] = 0.f;
    for (int k = b; k < e; k++) {
        int i = g_adj[k], d = e1[i];
#pragma unroll
        for (int h = 0; h < HT; h++)
            a[h] += (g_alpha[i * HT + h] / ssv[h]) * g_eout[(size_t)(d * HT + h) * HH + c];
    }
    float v = 0.f;
#pragma unroll
    for (int h = 0; h < HT; h++) v += a[h];
    v = v * g_Dinv[s] * (1.f / HT) + bias[c];
    out[s * HH + c] = (v > 0.f) ? v : 0.2f * v;
}

__global__ void head_k(const float* __restrict__ x2, const float* __restrict__ Wo,
                       const float* __restrict__ bo, float* __restrict__ out) {
    int n = blockIdx.x * 4 + (threadIdx.x >> 5), lane = threadIdx.x & 31;
    float s = 0.f;
#pragma unroll
    for (int m = 0; m < 4; m++) s += x2[n * HH + lane + 32 * m] * Wo[lane + 32 * m];
#pragma unroll
    for (int o = 16; o; o >>= 1) s += __shfl_xor_sync(0xffffffffu, s, o);
    if (!lane) {
        float v = s + bo[0];
        out[n] = (v > 0.f) ? v : 0.01f * v;
    }
}

// ----------------- host -----------------
static void* sym(const void* s) { void* p = 0; cudaGetSymbolAddress(&p, s); return p; }

extern "C" void kernel_launch(void* const* d_in, const int* in_sizes, int n_in,
                              void* d_out, int out_size) {
    const float* price = (const float*)d_in[0];
    const int*   e     = (const int*)d_in[1];
    const float* bn1g  = (const float*)d_in[2];
    const float* bn1b  = (const float*)d_in[3];
    const float* Wih   = (const float*)d_in[4];
    const float* Whh   = (const float*)d_in[5];
    const float* bih   = (const float*)d_in[6];
    const float* bhh   = (const float*)d_in[7];
    const float* Wq    = (const float*)d_in[8];
    const float* Wout  = (const float*)d_in[9];
    const float* ae    = (const float*)d_in[10];
    const float* ab    = (const float*)d_in[11];
    const float* bn2g  = (const float*)d_in[12];
    const float* bn2b  = (const float*)d_in[13];
    const float* W1    = (const float*)d_in[14];
    const float* att1  = (const float*)d_in[15];
    const float* bias1 = (const float*)d_in[16];
    const float* W2    = (const float*)d_in[17];
    const float* att2  = (const float*)d_in[18];
    const float* bias2 = (const float*)d_in[19];
    const float* Wo    = (const float*)d_in[20];
    const float* bo    = (const float*)d_in[21];
    const int* e0 = e;
    const int* e1 = e + NZ;

    float* out_nf = (float*)d_out;
    float* out_x  = out_nf + NH;
    float* out_o  = out_x + NH;

    float* p_sum1 = (float*)sym(g_sum1);   float* p_sq1 = (float*)sym(g_sq1);
    float* p_sum2 = (float*)sym(g_sum2);   float* p_sq2 = (float*)sym(g_sq2);
    float* p_sc1 = (float*)sym(g_scale1);  float* p_sh1 = (float*)sym(g_shift1);
    float* p_sc2 = (float*)sym(g_scale2);  float* p_sh2 = (float*)sym(g_shift2);
    float* p_h0 = (float*)sym(g_h0);
    float* p_q = (float*)sym(g_q);         float* p_comb = (float*)sym(g_comb);
    float* p_xbn = (float*)sym(g_xbn);     float* p_ef = (float*)sym(g_ef);
    float* p_xw = (float*)sym(g_xw);       float* p_ew = (float*)sym(g_ew);
    float* p_xa = (float*)sym(g_xa);       float* p_ea = (float*)sym(g_ea);
    unsigned* p_smax = (unsigned*)sym(g_segmax);
    float* p_ssum = (float*)sym(g_segsum);
    float* p_x1 = (float*)sym(g_x1);
    int* p_cnt = (int*)sym(g_cnt);         int* p_cur = (int*)sym(g_cursor);
    int* p_rp = (int*)sym(g_rowptr);       int* p_adj = (int*)sym(g_adj);
    float* p_Dinv = (float*)sym(g_Dinv);

    // launches 1-3, so launch #4 (ncu capture slot) = gru_persist
    bn_stats<<<16, 1024>>>(price, 512, p_sum1, p_sq1);
    bn_finalize<<<4, 128>>>(p_sum1, p_sq1, bn1g, bn1b, p_sc1, p_sh1, 512);
    prep_all<<<704, 256>>>(Whh, Wih, bih, bhh);

    gru_persist<<<128, 512>>>(price);   // full 32-step GRU, hT -> g_h0, ctx -> g_ctx

    gemm_tf32<<<dim3(2, 64), 256>>>(p_h0, Wq, p_q, NN, 128, 128, 0);
    attn_mid<<<NN, 128>>>(ae, ab);
    gemm_tf32<<<dim3(2, 64), 256>>>(p_comb, Wout, out_nf, NN, 128, 256, 1);

    bn_stats<<<4, 1024>>>(out_nf, 128, p_sum2, p_sq2);
    bn_finalize<<<1, 128>>>(p_sum2, p_sq2, bn2g, bn2b, p_sc2, p_sh2, 128);
    bn_apply<<<NH / 256, 256>>>(out_nf, p_sc2, p_sh2, p_xbn, p_cnt);

    // CSR by src
    count_src<<<NZ / 256, 256>>>(e0, p_cnt);
    scan_csr<<<1, 1024>>>(p_cnt, p_rp, p_Dinv, p_cur);
    fill_csr<<<NZ / 256, 256>>>(e0, p_rp, p_cur, p_adj, p_smax, p_ssum);

    // ---- conv 1 (4 heads) ----
    efeat<<<EE, 128>>>(e0, p_xbn, p_ef, p_smax, p_ssum, 0);
    gemm_tf32<<<dim3(8, 64), 256>>>(p_xbn, W1, p_xw, NN, 512, 128, 0);
    gemm_tf32<<<dim3(8, 16), 256>>>(p_ef, W1, p_ew, EE, 512, 128, 0);
    rowdot<<<NN, 128>>>(p_xw, att1, 256, NHEADS, p_xa);
    rowdot<<<EE, 128>>>(p_ew, att1 + 128, 256, NHEADS, p_ea);
    alpha_max<<<NZ * NHEADS / 256, 256>>>(e0, e1, p_xa, p_ea, NHEADS);
    alpha_exp<<<NZ * NHEADS / 256, 256>>>(e0, NHEADS);
    eout_gather<NHEADS><<<EE, 128>>>(e0, p_xw);
    node_out<NHEADS><<<NN, 128>>>(e1, bias1, p_x1);

    // ---- conv 2 (1 head) ----
    efeat<<<EE, 128>>>(e0, p_x1, p_ef, p_smax, p_ssum, 1);
    gemm_tf32<<<dim3(2, 64), 256>>>(p_x1, W2, p_xw, NN, 128, 128, 0);
    gemm_tf32<<<dim3(2, 16), 256>>>(p_ef, W2, p_ew, EE, 128, 128, 0);
    rowdot<<<NN, 32>>>(p_xw, att2, 256, 1, p_xa);
    rowdot<<<EE, 32>>>(p_ew, att2 + 128, 256, 1, p_ea);
    alpha_max<<<NZ / 256, 256>>>(e0, e1, p_xa, p_ea, 1);
    alpha_exp<<<NZ / 256, 256>>>(e0, 1);
    eout_gather<1><<<EE, 128>>>(e0, p_xw);
    node_out<1><<<NN, 128>>>(e1, bias2, out_x);

    head_k<<<NN / 4, 128>>>(out_x, Wo, bo, out_o);
}

// round 15
// speedup vs baseline: 1.1084x; 1.1084x over previous
#include <cuda_runtime.h>
#include <math.h>

#define NN 8192
#define TT 32
#define FF 16
#define HH 128
#define NHEADS 4
#define EE 2048
#define NZ 65536
#define NH (NN*HH)

// ----------------- static device scratch (no allocs) -----------------
__device__ float g_scale1[512], g_shift1[512], g_sum1[512], g_sq1[512];
__device__ float g_scale2[HH], g_shift2[HH], g_sum2[HH], g_sq2[HH];
__device__ float g_WfragH[64 * 16 * 32 * 2];       // tf32 B-frags, h-part (256KB)
__device__ float g_WfragX[32 * 64 * 2 * 32 * 2];   // tf32 B-frags, x-part per t (1MB)
__device__ float g_bias[32 * 512];                 // combined per-t bias
__device__ float g_h0[NH];
__device__ float g_ctx[NN * TT * HH];
__device__ float g_q[NH];
__device__ float g_comb[NN * 2 * HH];
__device__ float g_xbn[NH];
__device__ float g_ef[EE * HH];
__device__ float g_xw[NN * 512];
__device__ float g_ew[EE * 512];
__device__ float g_xa[NN * NHEADS];
__device__ float g_ea[EE * NHEADS];
__device__ float g_alpha[NZ * NHEADS];
__device__ unsigned g_segmax[NN * NHEADS];
__device__ float g_segsum[NN * NHEADS];
__device__ float g_Dinv[NN];
__device__ float g_eout[EE * NHEADS * HH];
__device__ float g_x1[NH];
__device__ int g_cnt[NN], g_cursor[NN], g_rowptr[NN + 1], g_adj[NZ];

// ----------------- helpers -----------------
__device__ __forceinline__ unsigned fenc(float a) {
    unsigned u = __float_as_uint(a);
    return (u & 0x80000000u) ? ~u : (u | 0x80000000u);
}
__device__ __forceinline__ float fdec(unsigned u) {
    return (u & 0x80000000u) ? __uint_as_float(u & 0x7FFFFFFFu) : __uint_as_float(~u);
}
__device__ __forceinline__ float tf32r(float x) {
    unsigned u; asm("cvt.rna.tf32.f32 %0, %1;" : "=r"(u) : "f"(x));
    return __uint_as_float(u);
}
__device__ __forceinline__ float sigacc(float x) {
    return __fdividef(1.f, 1.f + __expf(-x));
}
__device__ __forceinline__ float tanhacc(float x) {
    return 1.f - __fdividef(2.f, __expf(2.f * x) + 1.f);
}
__device__ __forceinline__ void mma8(float* c, const unsigned* a, unsigned b0, unsigned b1) {
    asm volatile(
        "mma.sync.aligned.m16n8k8.row.col.f32.tf32.tf32.f32 "
        "{%0,%1,%2,%3}, {%4,%5,%6,%7}, {%8,%9}, {%0,%1,%2,%3};\n"
        : "+f"(c[0]), "+f"(c[1]), "+f"(c[2]), "+f"(c[3])
        : "r"(a[0]), "r"(a[1]), "r"(a[2]), "r"(a[3]), "r"(b0), "r"(b1));
}

// ----------------- batchnorm -----------------
__global__ void bn_stats(const float* __restrict__ x, int ncols, float* sum, float* sq) {
    __shared__ float ssum[32 * 33], ssq[32 * 33];
    int c = threadIdx.x & 31, rg = threadIdx.x >> 5;
    int col = blockIdx.x * 32 + c;
    float s = 0.f, q = 0.f;
    for (int r = rg; r < NN; r += 32) {
        float v = x[(size_t)r * ncols + col];
        s += v; q += v * v;
    }
    ssum[rg * 33 + c] = s; ssq[rg * 33 + c] = q;
    __syncthreads();
    if (threadIdx.x < 32) {
        float S = 0.f, Q = 0.f;
        for (int g = 0; g < 32; g++) { S += ssum[g * 33 + threadIdx.x]; Q += ssq[g * 33 + threadIdx.x]; }
        sum[blockIdx.x * 32 + threadIdx.x] = S;
        sq[blockIdx.x * 32 + threadIdx.x] = Q;
    }
}
__global__ void bn_finalize(const float* sum, const float* sq, const float* g,
                            const float* b, float* scale, float* shift, int ncols) {
    int c = blockIdx.x * blockDim.x + threadIdx.x;
    if (c >= ncols) return;
    float m = sum[c] * (1.f / NN);
    float v = sq[c] * (1.f / NN) - m * m;
    float sc = rsqrtf(v + 1e-5f) * g[c];
    scale[c] = sc; shift[c] = b[c] - m * sc;
}
__global__ void bn_apply(const float* __restrict__ x, const float* scale,
                         const float* shift, float* y, int* cnt) {
    int i = blockIdx.x * blockDim.x + threadIdx.x;
    if (i >= NH) return;
    int c = i & (HH - 1);
    y[i] = x[i] * scale[c] + shift[c];
    if (i < NN) cnt[i] = 0;
}

// ----------------- GRU prep: fragment-ready tf32 weights + biases -----------------
__global__ void prep_all(const float* __restrict__ Whh, const float* __restrict__ Wih,
                         const float* __restrict__ bih, const float* __restrict__ bhh) {
    int b = blockIdx.x, tid = threadIdx.x;
    if (b < 128) {                       // WfragH: [ntg 64][ks 16][lane 32][2]
        int idx = b * 256 + tid;
        int lane = idx & 31, ks = (idx >> 5) & 15, ntg = idx >> 9;
        int k = ks * 8 + (lane & 3), c = ntg * 8 + (lane >> 2);
        int j = c >> 2, p = c & 3;
        float b0 = 0.f, b1 = 0.f;
        if (p != 2) {
            int g = (p == 3) ? (256 + j) : (p * 128 + j);
            b0 = Whh[g * 128 + k]; b1 = Whh[g * 128 + k + 4];
        }
        g_WfragH[idx * 2] = tf32r(b0); g_WfragH[idx * 2 + 1] = tf32r(b1);
    } else if (b < 640) {                // WfragX: [t 32][ntg 64][ks2 2][lane 32][2]
        int idx = (b - 128) * 256 + tid;
        int lane = idx & 31, ks2 = (idx >> 5) & 1, ntg = (idx >> 6) & 63, t = idx >> 12;
        int f = ks2 * 8 + (lane & 3), c = ntg * 8 + (lane >> 2);
        int j = c >> 2, p = c & 3;
        float b0 = 0.f, b1 = 0.f;
        if (p != 3) {
            int g = p * 128 + j;
            b0 = Wih[g * 16 + f] * g_scale1[t * 16 + f];
            b1 = Wih[g * 16 + f + 4] * g_scale1[t * 16 + f + 4];
        }
        g_WfragX[idx * 2] = tf32r(b0); g_WfragX[idx * 2 + 1] = tf32r(b1);
    } else {                             // bias: [t 32][c 512]
        int idx = (b - 640) * 256 + tid;
        int c = idx & 511, t = idx >> 9;
        int j = c >> 2, p = c & 3;
        float v;
        if (p == 3) v = bhh[256 + j];
        else {
            int g = p * 128 + j;
            float sd = 0.f;
            for (int f = 0; f < 16; f++) sd += g_shift1[t * 16 + f] * Wih[g * 16 + f];
            v = bih[g] + sd + ((p < 2) ? bhh[g] : 0.f);
        }
        g_bias[t * 512 + c] = v;
    }
}

// ----------------- persistent tf32-mma GRU (512 threads, 16 warps, 2-deep B prefetch) ----
#define GPAD 132
__device__ __forceinline__ void loadBfrag(float2* dst, const float2* WH, const float2* WXt,
                                          int warp, int lane, int kn) {
    if (kn < 16) {
#pragma unroll
        for (int nt = 0; nt < 4; nt++)
            dst[nt] = WH[(((warp * 4 + nt) * 16) + kn) * 32 + lane];
    } else {
        int ks2 = kn - 16;
#pragma unroll
        for (int nt = 0; nt < 4; nt++)
            dst[nt] = WXt[(((warp * 4 + nt) * 2) + ks2) * 32 + lane];
    }
}
__global__ void __launch_bounds__(512)
gru_persist(const float* __restrict__ price) {
    __shared__ float sh[64 * GPAD];
    __shared__ float sx[64 * 20];
    __shared__ float sbias[512];
    int tid = threadIdx.x, lane = tid & 31, warp = tid >> 5;
    int gid = lane >> 2, q = lane & 3;
    int node0 = blockIdx.x * 64;

    for (int i = tid; i < 64 * GPAD; i += 512) sh[i] = 0.f;
    __syncthreads();

    const float2* __restrict__ WH = (const float2*)g_WfragH;

    for (int t = 0; t < TT; t++) {
        for (int i = tid; i < 1024; i += 512) {
            int nd = i >> 4, f = i & 15;
            sx[nd * 20 + f] = tf32r(price[(size_t)(node0 + nd) * 512 + t * 16 + f]);
        }
        if (tid < 512) sbias[tid] = g_bias[t * 512 + tid];
        __syncthreads();   // A

        const float2* __restrict__ WXt = (const float2*)g_WfragX + (size_t)t * 4096;

        float acc[4][4][4];
#pragma unroll
        for (int mt = 0; mt < 4; mt++)
#pragma unroll
            for (int nt = 0; nt < 4; nt++) {
                int cb = warp * 32 + nt * 8 + 2 * q;
                float2 bv = *(const float2*)&sbias[cb];
                acc[mt][nt][0] = bv.x; acc[mt][nt][1] = bv.y;
                acc[mt][nt][2] = bv.x; acc[mt][nt][3] = bv.y;
            }

        // 2-deep B prefetch ring
        float2 bbuf[2][4];
        loadBfrag(bbuf[0], WH, WXt, warp, lane, 0);
        loadBfrag(bbuf[1], WH, WXt, warp, lane, 1);

#pragma unroll
        for (int ks = 0; ks < 18; ks++) {
            float2 bu[4];
#pragma unroll
            for (int nt = 0; nt < 4; nt++) bu[nt] = bbuf[ks & 1][nt];
            if (ks < 16)
                loadBfrag(bbuf[ks & 1], WH, WXt, warp, lane, ks + 2);

            unsigned a[4][4];
            if (ks < 16) {
                int base = ks * 8 + q;
#pragma unroll
                for (int mt = 0; mt < 4; mt++) {
                    int r0 = mt * 16 + gid;
                    a[mt][0] = __float_as_uint(sh[r0 * GPAD + base]);
                    a[mt][1] = __float_as_uint(sh[(r0 + 8) * GPAD + base]);
                    a[mt][2] = __float_as_uint(sh[r0 * GPAD + base + 4]);
                    a[mt][3] = __float_as_uint(sh[(r0 + 8) * GPAD + base + 4]);
                }
            } else {
                int base = (ks - 16) * 8 + q;
#pragma unroll
                for (int mt = 0; mt < 4; mt++) {
                    int r0 = mt * 16 + gid;
                    a[mt][0] = __float_as_uint(sx[r0 * 20 + base]);
                    a[mt][1] = __float_as_uint(sx[(r0 + 8) * 20 + base]);
                    a[mt][2] = __float_as_uint(sx[r0 * 20 + base + 4]);
                    a[mt][3] = __float_as_uint(sx[(r0 + 8) * 20 + base + 4]);
                }
            }
#pragma unroll
            for (int nt = 0; nt < 4; nt++) {
                unsigned b0 = __float_as_uint(bu[nt].x), b1 = __float_as_uint(bu[nt].y);
#pragma unroll
                for (int mt = 0; mt < 4; mt++) mma8(acc[mt][nt], a[mt], b0, b1);
            }
        }

        __syncthreads();   // B

#pragma unroll
        for (int mt = 0; mt < 4; mt++)
#pragma unroll
            for (int nt = 0; nt < 4; nt++) {
                float c0 = acc[mt][nt][0], c1 = acc[mt][nt][1];
                float c2 = acc[mt][nt][2], c3 = acc[mt][nt][3];
                float v0 = __shfl_xor_sync(0xffffffffu, c0, 1);
                float v1 = __shfl_xor_sync(0xffffffffu, c1, 1);
                float v2 = __shfl_xor_sync(0xffffffffu, c2, 1);
                float v3 = __shfl_xor_sync(0xffffffffu, c3, 1);
                int cb = warp * 32 + nt * 8 + 2 * q;
                int j = cb >> 2;
                float ra, za, nx, nh; int row;
                if ((q & 1) == 0) { row = mt * 16 + gid;     ra = c0; za = c1; nx = v0; nh = v1; }
                else              { row = mt * 16 + gid + 8; ra = v2; za = v3; nx = c2; nh = c3; }
                float r = sigacc(ra), z = sigacc(za);
                float n = tanhacc(nx + r * nh);
                float hold = sh[row * GPAD + j];
                sh[row * GPAD + j] = tf32r((1.f - z) * n + z * hold);
            }
        __syncthreads();   // C

        size_t cbase = (size_t)node0 * 4096 + (size_t)t * 128;
        for (int i = tid; i < 2048; i += 512) {
            int nd = i >> 5, jq = i & 31;
            float4 v = *(const float4*)&sh[nd * GPAD + jq * 4];
            *(float4*)&g_ctx[cbase + (size_t)nd * 4096 + jq * 4] = v;
            if (t == 31) *(float4*)&g_h0[(size_t)(node0 + nd) * 128 + jq * 4] = v;
        }
    }
}

// ----------------- generic NT sgemm: C = act(A(M,K) @ B(Nc,K)^T) -----------------
__global__ void gemm_nt(const float* __restrict__ A, const float* __restrict__ B,
                        float* __restrict__ C, int M, int Nc, int K, int act) {
    __shared__ float As[16 * 68], Bs[16 * 68];
    int tid = threadIdx.x, n0 = blockIdx.x * 64, m0 = blockIdx.y * 64;
    int lrow = tid >> 2, kq = tid & 3, tx = tid & 15, ty = tid >> 4;
    float c[4][4];
#pragma unroll
    for (int i = 0; i < 4; i++)
#pragma unroll
        for (int jv = 0; jv < 4; jv++) c[i][jv] = 0.f;

    for (int k0 = 0; k0 < K; k0 += 16) {
        float4 av = *(const float4*)&A[(size_t)(m0 + lrow) * K + k0 + kq * 4];
        float4 bv = *(const float4*)&B[(size_t)(n0 + lrow) * K + k0 + kq * 4];
        __syncthreads();
        As[(kq*4+0)*68+lrow] = av.x; As[(kq*4+1)*68+lrow] = av.y;
        As[(kq*4+2)*68+lrow] = av.z; As[(kq*4+3)*68+lrow] = av.w;
        Bs[(kq*4+0)*68+lrow] = bv.x; Bs[(kq*4+1)*68+lrow] = bv.y;
        Bs[(kq*4+2)*68+lrow] = bv.z; Bs[(kq*4+3)*68+lrow] = bv.w;
        __syncthreads();
#pragma unroll
        for (int kk = 0; kk < 16; kk++) {
            float4 a = *(const float4*)&As[kk * 68 + ty * 4];
            float4 b = *(const float4*)&Bs[kk * 68 + tx * 4];
            float ar[4] = {a.x, a.y, a.z, a.w}, br[4] = {b.x, b.y, b.z, b.w};
#pragma unroll
            for (int i = 0; i < 4; i++)
#pragma unroll
                for (int jv = 0; jv < 4; jv++) c[i][jv] += ar[i] * br[jv];
        }
    }
#pragma unroll
    for (int i = 0; i < 4; i++)
#pragma unroll
        for (int jv = 0; jv < 4; jv++) {
            float v = c[i][jv];
            if (act == 1) v = tanhf(v);
            C[(size_t)(m0 + ty * 4 + i) * Nc + n0 + tx * 4 + jv] = v;
        }
}

// ----------------- temporal attention middle -----------------
__global__ void attn_mid(const float* __restrict__ ae, const float* __restrict__ ab) {
    __shared__ float sctx[32 * 129], sq[128], sw[32], sbt[32];
    int n = blockIdx.x, tid = threadIdx.x;
    sq[tid] = g_q[n * HH + tid];
    for (int idx = tid; idx < TT * HH; idx += 128) {
        int t = idx >> 7, k = idx & 127;
        sctx[t * 129 + k] = g_ctx[(size_t)n * (TT * HH) + idx];
    }
    __syncthreads();
    if (tid < 32) {
        float s = 0.f;
        for (int k = 0; k < 128; k++) s += sq[k] * sctx[tid * 129 + k];
        float m = s;
#pragma unroll
        for (int o = 16; o; o >>= 1) m = fmaxf(m, __shfl_xor_sync(0xffffffffu, m, o));
        float e = expf(s - m), su = e;
#pragma unroll
        for (int o = 16; o; o >>= 1) su += __shfl_xor_sync(0xffffffffu, su, o);
        sw[tid] = e / su;
        sbt[tid] = expf(-ab[n] * (float)(31 - tid));
    }
    __syncthreads();
    float aen = ae[n], acc = 0.f;
#pragma unroll 4
    for (int t = 0; t < TT; t++) {
        float mx = sw[t] * sctx[t * 129 + tid];
        acc += mx + fmaxf(aen * mx * sbt[t], 0.f);
    }
    g_comb[n * 256 + tid] = acc;
    g_comb[n * 256 + 128 + tid] = sq[tid];
}

// ----------------- CSR build (by src) -----------------
__global__ void count_src(const int* __restrict__ e0, int* cnt) {
    int i = blockIdx.x * blockDim.x + threadIdx.x;
    if (i < NZ) atomicAdd(&cnt[e0[i]], 1);
}
__global__ void scan_csr(const int* __restrict__ cnt, int* rowptr, float* Dinv, int* cursor) {
    __shared__ int s[1024];
    int tid = threadIdx.x, base = tid * 8, loc[8], sum = 0;
#pragma unroll
    for (int j = 0; j < 8; j++) { loc[j] = sum; sum += cnt[base + j]; }
    s[tid] = sum;
    __syncthreads();
    for (int off = 1; off < 1024; off <<= 1) {
        int v = (tid >= off) ? s[tid - off] : 0;
        __syncthreads();
        s[tid] += v;
        __syncthreads();
    }
    int excl = tid ? s[tid - 1] : 0;
#pragma unroll
    for (int j = 0; j < 8; j++) {
        rowptr[base + j] = excl + loc[j];
        int c = cnt[base + j];
        Dinv[base + j] = c ? 1.f / (float)c : 0.f;
        cursor[base + j] = 0;
    }
    if (tid == 1023) rowptr[NN] = s[1023];
}
__global__ void fill_csr(const int* __restrict__ e0, const int* __restrict__ rowptr,
                         int* cursor, int* adj, unsigned* segmax, float* segsum) {
    int i = blockIdx.x * blockDim.x + threadIdx.x;
    if (i >= NZ) return;
    if (i < NN * NHEADS) { segmax[i] = 0u; segsum[i] = 0.f; }
    int sg = e0[i];
    int p = atomicAdd(&cursor[sg], 1);
    adj[rowptr[sg] + p] = i;
}

// ----------------- hypergraph pieces -----------------
__global__ void efeat(const int* __restrict__ e0, const float* __restrict__ x, float* ef,
                      unsigned* segmax, float* segsum, int zeroseg) {
    int d = blockIdx.x, c = threadIdx.x;
    if (zeroseg) {
        int gid = d * 128 + c;
        if (gid < NN) { segmax[gid] = 0u; segsum[gid] = 0.f; }
    }
    float a = 0.f;
#pragma unroll 4
    for (int j = 0; j < 32; j++) a += x[e0[d + j * EE] * HH + c];
    ef[d * HH + c] = a;
}

__global__ void rowdot(const float* __restrict__ xw, const float* __restrict__ att,
                       int stride, int heads, float* __restrict__ out) {
    int r = blockIdx.x, h = threadIdx.x >> 5, lane = threadIdx.x & 31;
    const float* row = xw + (size_t)(r * heads + h) * HH;
    float s = 0.f;
#pragma unroll
    for (int m = 0; m < 4; m++) s += row[lane + 32 * m] * att[h * stride + lane + 32 * m];
#pragma unroll
    for (int o = 16; o; o >>= 1) s += __shfl_xor_sync(0xffffffffu, s, o);
    if (!lane) out[r * heads + h] = s;
}

__global__ void alpha_max(const int* __restrict__ e0, const int* __restrict__ e1,
                          const float* __restrict__ xa, const float* __restrict__ ea,
                          int heads) {
    int g = blockIdx.x * blockDim.x + threadIdx.x;
    if (g >= NZ * heads) return;
    int i = g / heads, h = g - i * heads;
    float a = xa[e0[i] * heads + h] + ea[e1[i] * heads + h];
    a = (a > 0.f) ? a : 0.2f * a;
    g_alpha[g] = a;
    atomicMax(&g_segmax[e0[i] * heads + h], fenc(a));
}
__global__ void alpha_exp(const int* __restrict__ e0, int heads) {
    int g = blockIdx.x * blockDim.x + threadIdx.x;
    if (g >= NZ * heads) return;
    int i = g / heads, h = g - i * heads;
    float ex = expf(g_alpha[g] - fdec(g_segmax[e0[i] * heads + h]));
    g_alpha[g] = ex;
    atomicAdd(&g_segsum[e0[i] * heads + h], ex);
}

template <int HT>
__global__ void eout_gather(const int* __restrict__ e0, const float* __restrict__ xw) {
    int d = blockIdx.x, c = threadIdx.x;
    float acc[HT];
#pragma unroll
    for (int h = 0; h < HT; h++) acc[h] = 0.f;
    for (int j = 0; j < 32; j++) {
        int i = d + j * EE, s = e0[i];
#pragma unroll
        for (int h = 0; h < HT; h++) {
            float an = g_alpha[i * HT + h] / (g_segsum[s * HT + h] + 1e-16f);
            acc[h] += an * xw[(size_t)(s * HT + h) * HH + c];
        }
    }
#pragma unroll
    for (int h = 0; h < HT; h++)
        g_eout[(size_t)(d * HT + h) * HH + c] = acc[h] * (1.f / 32.f);
}

template <int HT>
__global__ void node_out(const int* __restrict__ e1, const float* __restrict__ bias,
                         float* __restrict__ out) {
    int s = blockIdx.x, c = threadIdx.x;
    int b = g_rowptr[s], e = g_rowptr[s + 1];
    float ssv[HT];
#pragma unroll
    for (int h = 0; h < HT; h++) ssv[h] = g_segsum[s * HT + h] + 1e-16f;
    float a[HT];
#pragma unroll
    for (int h = 0; h < HT; h++) a[h] = 0.f;
    for (int k = b; k < e; k++) {
        int i = g_adj[k], d = e1[i];
#pragma unroll
        for (int h = 0; h < HT; h++)
            a[h] += (g_alpha[i * HT + h] / ssv[h]) * g_eout[(size_t)(d * HT + h) * HH + c];
    }
    float v = 0.f;
#pragma unroll
    for (int h = 0; h < HT; h++) v += a[h];
    v = v * g_Dinv[s] * (1.f / HT) + bias[c];
    out[s * HH + c] = (v > 0.f) ? v : 0.2f * v;
}

__global__ void head_k(const float* __restrict__ x2, const float* __restrict__ Wo,
                       const float* __restrict__ bo, float* __restrict__ out) {
    int n = blockIdx.x * 4 + (threadIdx.x >> 5), lane = threadIdx.x & 31;
    float s = 0.f;
#pragma unroll
    for (int m = 0; m < 4; m++) s += x2[n * HH + lane + 32 * m] * Wo[lane + 32 * m];
#pragma unroll
    for (int o = 16; o; o >>= 1) s += __shfl_xor_sync(0xffffffffu, s, o);
    if (!lane) {
        float v = s + bo[0];
        out[n] = (v > 0.f) ? v : 0.01f * v;
    }
}

// ----------------- host -----------------
static void* sym(const void* s) { void* p = 0; cudaGetSymbolAddress(&p, s); return p; }

extern "C" void kernel_launch(void* const* d_in, const int* in_sizes, int n_in,
                              void* d_out, int out_size) {
    const float* price = (const float*)d_in[0];
    const int*   e     = (const int*)d_in[1];
    const float* bn1g  = (const float*)d_in[2];
    const float* bn1b  = (const float*)d_in[3];
    const float* Wih   = (const float*)d_in[4];
    const float* Whh   = (const float*)d_in[5];
    const float* bih   = (const float*)d_in[6];
    const float* bhh   = (const float*)d_in[7];
    const float* Wq    = (const float*)d_in[8];
    const float* Wout  = (const float*)d_in[9];
    const float* ae    = (const float*)d_in[10];
    const float* ab    = (const float*)d_in[11];
    const float* bn2g  = (const float*)d_in[12];
    const float* bn2b  = (const float*)d_in[13];
    const float* W1    = (const float*)d_in[14];
    const float* att1  = (const float*)d_in[15];
    const float* bias1 = (const float*)d_in[16];
    const float* W2    = (const float*)d_in[17];
    const float* att2  = (const float*)d_in[18];
    const float* bias2 = (const float*)d_in[19];
    const float* Wo    = (const float*)d_in[20];
    const float* bo    = (const float*)d_in[21];
    const int* e0 = e;
    const int* e1 = e + NZ;

    float* out_nf = (float*)d_out;
    float* out_x  = out_nf + NH;
    float* out_o  = out_x + NH;

    float* p_sum1 = (float*)sym(g_sum1);   float* p_sq1 = (float*)sym(g_sq1);
    float* p_sum2 = (float*)sym(g_sum2);   float* p_sq2 = (float*)sym(g_sq2);
    float* p_sc1 = (float*)sym(g_scale1);  float* p_sh1 = (float*)sym(g_shift1);
    float* p_sc2 = (float*)sym(g_scale2);  float* p_sh2 = (float*)sym(g_shift2);
    float* p_h0 = (float*)sym(g_h0);
    float* p_q = (float*)sym(g_q);         float* p_comb = (float*)sym(g_comb);
    float* p_xbn = (float*)sym(g_xbn);     float* p_ef = (float*)sym(g_ef);
    float* p_xw = (float*)sym(g_xw);       float* p_ew = (float*)sym(g_ew);
    float* p_xa = (float*)sym(g_xa);       float* p_ea = (float*)sym(g_ea);
    unsigned* p_smax = (unsigned*)sym(g_segmax);
    float* p_ssum = (float*)sym(g_segsum);
    float* p_x1 = (float*)sym(g_x1);
    int* p_cnt = (int*)sym(g_cnt);         int* p_cur = (int*)sym(g_cursor);
    int* p_rp = (int*)sym(g_rowptr);       int* p_adj = (int*)sym(g_adj);
    float* p_Dinv = (float*)sym(g_Dinv);

    // launches 1-3, so launch #4 (ncu capture slot) = gru_persist
    bn_stats<<<16, 1024>>>(price, 512, p_sum1, p_sq1);
    bn_finalize<<<4, 128>>>(p_sum1, p_sq1, bn1g, bn1b, p_sc1, p_sh1, 512);
    prep_all<<<704, 256>>>(Whh, Wih, bih, bhh);

    gru_persist<<<128, 512>>>(price);   // full 32-step GRU, hT -> g_h0, ctx -> g_ctx

    gemm_nt<<<dim3(2, NN / 64), 256>>>(p_h0, Wq, p_q, NN, 128, 128, 0);
    attn_mid<<<NN, 128>>>(ae, ab);
    gemm_nt<<<dim3(2, NN / 64), 256>>>(p_comb, Wout, out_nf, NN, 128, 256, 1);

    bn_stats<<<4, 1024>>>(out_nf, 128, p_sum2, p_sq2);
    bn_finalize<<<1, 128>>>(p_sum2, p_sq2, bn2g, bn2b, p_sc2, p_sh2, 128);
    bn_apply<<<NH / 256, 256>>>(out_nf, p_sc2, p_sh2, p_xbn, p_cnt);

    // CSR by src
    count_src<<<NZ / 256, 256>>>(e0, p_cnt);
    scan_csr<<<1, 1024>>>(p_cnt, p_rp, p_Dinv, p_cur);
    fill_csr<<<NZ / 256, 256>>>(e0, p_rp, p_cur, p_adj, p_smax, p_ssum);

    // ---- conv 1 (4 heads) ----
    efeat<<<EE, 128>>>(e0, p_xbn, p_ef, p_smax, p_ssum, 0);
    gemm_nt<<<dim3(8, NN / 64), 256>>>(p_xbn, W1, p_xw, NN, 512, 128, 0);
    gemm_nt<<<dim3(8, EE / 64), 256>>>(p_ef, W1, p_ew, EE, 512, 128, 0);
    rowdot<<<NN, 128>>>(p_xw, att1, 256, NHEADS, p_xa);
    rowdot<<<EE, 128>>>(p_ew, att1 + 128, 256, NHEADS, p_ea);
    alpha_max<<<NZ * NHEADS / 256, 256>>>(e0, e1, p_xa, p_ea, NHEADS);
    alpha_exp<<<NZ * NHEADS / 256, 256>>>(e0, NHEADS);
    eout_gather<NHEADS><<<EE, 128>>>(e0, p_xw);
    node_out<NHEADS><<<NN, 128>>>(e1, bias1, p_x1);

    // ---- conv 2 (1 head) ----
    efeat<<<EE, 128>>>(e0, p_x1, p_ef, p_smax, p_ssum, 1);
    gemm_nt<<<dim3(2, NN / 64), 256>>>(p_x1, W2, p_xw, NN, 128, 128, 0);
    gemm_nt<<<dim3(2, EE / 64), 256>>>(p_ef, W2, p_ew, EE, 128, 128, 0);
    rowdot<<<NN, 32>>>(p_xw, att2, 256, 1, p_xa);
    rowdot<<<EE, 32>>>(p_ew, att2 + 128, 256, 1, p_ea);
    alpha_max<<<NZ / 256, 256>>>(e0, e1, p_xa, p_ea, 1);
    alpha_exp<<<NZ / 256, 256>>>(e0, 1);
    eout_gather<1><<<EE, 128>>>(e0, p_xw);
    node_out<1><<<NN, 128>>>(e1, bias2, out_x);

    head_k<<<NN / 4, 128>>>(out_x, Wo, bo, out_o);
}

// round 17
// speedup vs baseline: 1.5702x; 1.4166x over previous
#include <cuda_runtime.h>
#include <math.h>

#define NN 8192
#define TT 32
#define FF 16
#define HH 128
#define NHEADS 4
#define EE 2048
#define NZ 65536
#define NH (NN*HH)

// ----------------- static device scratch (no allocs) -----------------
__device__ float g_scale1[512], g_shift1[512], g_sum1[512], g_sq1[512];
__device__ float g_scale2[HH], g_shift2[HH], g_sum2[HH], g_sq2[HH];
__device__ float g_WfragH[64 * 16 * 32 * 2];       // tf32 B-frags, h-part (256KB)
__device__ float g_WfragX[32 * 64 * 2 * 32 * 2];   // tf32 B-frags, x-part per t (1MB)
__device__ float g_bias[32 * 512];                 // combined per-t bias
__device__ float g_h0[NH];
__device__ float g_ctx[NN * TT * HH];
__device__ float g_q[NH];
__device__ float g_comb[NN * 2 * HH];
__device__ float g_xbn[NH];
__device__ float g_ef[EE * HH];
__device__ float g_xw[NN * 512];
__device__ float g_ew[EE * 512];
__device__ float g_xa[NN * NHEADS];
__device__ float g_ea[EE * NHEADS];
__device__ float g_alpha[NZ * NHEADS];
__device__ unsigned g_segmax[NN * NHEADS];
__device__ float g_segsum[NN * NHEADS];
__device__ float g_Dinv[NN];
__device__ float g_eout[EE * NHEADS * HH];
__device__ float g_x1[NH];
__device__ int g_cnt[NN], g_cursor[NN], g_rowptr[NN + 1], g_adj[NZ];

// ----------------- helpers -----------------
__device__ __forceinline__ unsigned fenc(float a) {
    unsigned u = __float_as_uint(a);
    return (u & 0x80000000u) ? ~u : (u | 0x80000000u);
}
__device__ __forceinline__ float fdec(unsigned u) {
    return (u & 0x80000000u) ? __uint_as_float(u & 0x7FFFFFFFu) : __uint_as_float(~u);
}
__device__ __forceinline__ float tf32r(float x) {
    unsigned u; asm("cvt.rna.tf32.f32 %0, %1;" : "=r"(u) : "f"(x));
    return __uint_as_float(u);
}
__device__ __forceinline__ float sigacc(float x) {
    return __fdividef(1.f, 1.f + __expf(-x));
}
__device__ __forceinline__ float tanhacc(float x) {
    return 1.f - __fdividef(2.f, __expf(2.f * x) + 1.f);
}
__device__ __forceinline__ void mma8(float* c, const unsigned* a, unsigned b0, unsigned b1) {
    asm volatile(
        "mma.sync.aligned.m16n8k8.row.col.f32.tf32.tf32.f32 "
        "{%0,%1,%2,%3}, {%4,%5,%6,%7}, {%8,%9}, {%0,%1,%2,%3};\n"
        : "+f"(c[0]), "+f"(c[1]), "+f"(c[2]), "+f"(c[3])
        : "r"(a[0]), "r"(a[1]), "r"(a[2]), "r"(a[3]), "r"(b0), "r"(b1));
}

// ----------------- batchnorm -----------------
__global__ void bn_stats(const float* __restrict__ x, int ncols, float* sum, float* sq) {
    __shared__ float ssum[32 * 33], ssq[32 * 33];
    int c = threadIdx.x & 31, rg = threadIdx.x >> 5;
    int col = blockIdx.x * 32 + c;
    float s = 0.f, q = 0.f;
    for (int r = rg; r < NN; r += 32) {
        float v = x[(size_t)r * ncols + col];
        s += v; q += v * v;
    }
    ssum[rg * 33 + c] = s; ssq[rg * 33 + c] = q;
    __syncthreads();
    if (threadIdx.x < 32) {
        float S = 0.f, Q = 0.f;
        for (int g = 0; g < 32; g++) { S += ssum[g * 33 + threadIdx.x]; Q += ssq[g * 33 + threadIdx.x]; }
        sum[blockIdx.x * 32 + threadIdx.x] = S;
        sq[blockIdx.x * 32 + threadIdx.x] = Q;
    }
}
__global__ void bn_finalize(const float* sum, const float* sq, const float* g,
                            const float* b, float* scale, float* shift, int ncols) {
    int c = blockIdx.x * blockDim.x + threadIdx.x;
    if (c >= ncols) return;
    float m = sum[c] * (1.f / NN);
    float v = sq[c] * (1.f / NN) - m * m;
    float sc = rsqrtf(v + 1e-5f) * g[c];
    scale[c] = sc; shift[c] = b[c] - m * sc;
}
__global__ void bn_apply(const float* __restrict__ x, const float* scale,
                         const float* shift, float* y, int* cnt) {
    int i = blockIdx.x * blockDim.x + threadIdx.x;
    if (i >= NH) return;
    int c = i & (HH - 1);
    y[i] = x[i] * scale[c] + shift[c];
    if (i < NN) cnt[i] = 0;
}

// ----------------- GRU prep: fragment-ready tf32 weights + biases -----------------
__global__ void prep_all(const float* __restrict__ Whh, const float* __restrict__ Wih,
                         const float* __restrict__ bih, const float* __restrict__ bhh) {
    int b = blockIdx.x, tid = threadIdx.x;
    if (b < 128) {                       // WfragH: [ntg 64][ks 16][lane 32][2]
        int idx = b * 256 + tid;
        int lane = idx & 31, ks = (idx >> 5) & 15, ntg = idx >> 9;
        int k = ks * 8 + (lane & 3), c = ntg * 8 + (lane >> 2);
        int j = c >> 2, p = c & 3;
        float b0 = 0.f, b1 = 0.f;
        if (p != 2) {
            int g = (p == 3) ? (256 + j) : (p * 128 + j);
            b0 = Whh[g * 128 + k]; b1 = Whh[g * 128 + k + 4];
        }
        g_WfragH[idx * 2] = tf32r(b0); g_WfragH[idx * 2 + 1] = tf32r(b1);
    } else if (b < 640) {                // WfragX: [t 32][ntg 64][ks2 2][lane 32][2]
        int idx = (b - 128) * 256 + tid;
        int lane = idx & 31, ks2 = (idx >> 5) & 1, ntg = (idx >> 6) & 63, t = idx >> 12;
        int f = ks2 * 8 + (lane & 3), c = ntg * 8 + (lane >> 2);
        int j = c >> 2, p = c & 3;
        float b0 = 0.f, b1 = 0.f;
        if (p != 3) {
            int g = p * 128 + j;
            b0 = Wih[g * 16 + f] * g_scale1[t * 16 + f];
            b1 = Wih[g * 16 + f + 4] * g_scale1[t * 16 + f + 4];
        }
        g_WfragX[idx * 2] = tf32r(b0); g_WfragX[idx * 2 + 1] = tf32r(b1);
    } else {                             // bias: [t 32][c 512]
        int idx = (b - 640) * 256 + tid;
        int c = idx & 511, t = idx >> 9;
        int j = c >> 2, p = c & 3;
        float v;
        if (p == 3) v = bhh[256 + j];
        else {
            int g = p * 128 + j;
            float sd = 0.f;
            for (int f = 0; f < 16; f++) sd += g_shift1[t * 16 + f] * Wih[g * 16 + f];
            v = bih[g] + sd + ((p < 2) ? bhh[g] : 0.f);
        }
        g_bias[t * 512 + c] = v;
    }
}

// ----------------- persistent tf32-mma GRU (two independent 32-node half-pipelines) ----
// grid 128 x 512. Warps 0-7 own nodes [0,32), warps 8-15 own [32,64) of the block's 64.
// Halves sync only via named barriers -> natural phase drift overlaps MUFU epilogue of
// one half with the HMMA mainloop of the other.
#define GPAD 132
__global__ void __launch_bounds__(512)
gru_persist(const float* __restrict__ price) {
    __shared__ float sh[64 * GPAD];
    __shared__ float sx[64 * 20];
    __shared__ float sbias[2][512];
    int tid = threadIdx.x, lane = tid & 31, warp = tid >> 5;
    int half = warp >> 3, hw = warp & 7;
    int htid = tid & 255;
    int gid = lane >> 2, q = lane & 3;
    int node0 = blockIdx.x * 64 + half * 32;
    float* shh = sh + half * 32 * GPAD;
    float* sxh = sx + half * 32 * 20;
    int bar = half + 1;

    for (int i = tid; i < 64 * GPAD; i += 512) sh[i] = 0.f;
    __syncthreads();

    const float2* __restrict__ WH = (const float2*)g_WfragH;

    for (int t = 0; t < TT; t++) {
        // stage x half-tile (32 nodes x 16 f) + bias copy
        for (int i = htid; i < 512; i += 256) {
            int nd = i >> 4, f = i & 15;
            sxh[nd * 20 + f] = tf32r(price[(size_t)(node0 + nd) * 512 + t * 16 + f]);
        }
        for (int i = htid; i < 512; i += 256) sbias[half][i] = g_bias[t * 512 + i];
        asm volatile("bar.sync %0, 256;" :: "r"(bar));   // A

        const float2* __restrict__ WXt = (const float2*)g_WfragX + (size_t)t * 4096;

        float acc[2][8][4];
#pragma unroll
        for (int mt = 0; mt < 2; mt++)
#pragma unroll
            for (int nt = 0; nt < 8; nt++) {
                int cb = hw * 64 + nt * 8 + 2 * q;
                float2 bv = *(const float2*)&sbias[half][cb];
                acc[mt][nt][0] = bv.x; acc[mt][nt][1] = bv.y;
                acc[mt][nt][2] = bv.x; acc[mt][nt][3] = bv.y;
            }

        float2 bcur[8], bnxt[8];
#pragma unroll
        for (int nt = 0; nt < 8; nt++)
            bcur[nt] = WH[(((hw * 8 + nt) * 16) + 0) * 32 + lane];

#pragma unroll
        for (int ks = 0; ks < 18; ks++) {
            if (ks < 17) {
                int kn = ks + 1;
                if (kn < 16) {
#pragma unroll
                    for (int nt = 0; nt < 8; nt++)
                        bnxt[nt] = WH[(((hw * 8 + nt) * 16) + kn) * 32 + lane];
                } else {
                    int ks2 = kn - 16;
#pragma unroll
                    for (int nt = 0; nt < 8; nt++)
                        bnxt[nt] = WXt[(((hw * 8 + nt) * 2) + ks2) * 32 + lane];
                }
            }
            unsigned a[2][4];
            if (ks < 16) {
                int base = ks * 8 + q;
#pragma unroll
                for (int mt = 0; mt < 2; mt++) {
                    int r0 = mt * 16 + gid;
                    a[mt][0] = __float_as_uint(shh[r0 * GPAD + base]);
                    a[mt][1] = __float_as_uint(shh[(r0 + 8) * GPAD + base]);
                    a[mt][2] = __float_as_uint(shh[r0 * GPAD + base + 4]);
                    a[mt][3] = __float_as_uint(shh[(r0 + 8) * GPAD + base + 4]);
                }
            } else {
                int base = (ks - 16) * 8 + q;
#pragma unroll
                for (int mt = 0; mt < 2; mt++) {
                    int r0 = mt * 16 + gid;
                    a[mt][0] = __float_as_uint(sxh[r0 * 20 + base]);
                    a[mt][1] = __float_as_uint(sxh[(r0 + 8) * 20 + base]);
                    a[mt][2] = __float_as_uint(sxh[r0 * 20 + base + 4]);
                    a[mt][3] = __float_as_uint(sxh[(r0 + 8) * 20 + base + 4]);
                }
            }
#pragma unroll
            for (int nt = 0; nt < 8; nt++) {
                unsigned b0 = __float_as_uint(bcur[nt].x), b1 = __float_as_uint(bcur[nt].y);
#pragma unroll
                for (int mt = 0; mt < 2; mt++) mma8(acc[mt][nt], a[mt], b0, b1);
            }
#pragma unroll
            for (int nt = 0; nt < 8; nt++) bcur[nt] = bnxt[nt];
        }

        asm volatile("bar.sync %0, 256;" :: "r"(bar));   // B

#pragma unroll
        for (int mt = 0; mt < 2; mt++)
#pragma unroll
            for (int nt = 0; nt < 8; nt++) {
                float c0 = acc[mt][nt][0], c1 = acc[mt][nt][1];
                float c2 = acc[mt][nt][2], c3 = acc[mt][nt][3];
                float v0 = __shfl_xor_sync(0xffffffffu, c0, 1);
                float v1 = __shfl_xor_sync(0xffffffffu, c1, 1);
                float v2 = __shfl_xor_sync(0xffffffffu, c2, 1);
                float v3 = __shfl_xor_sync(0xffffffffu, c3, 1);
                int cb = hw * 64 + nt * 8 + 2 * q;
                int j = cb >> 2;
                float ra, za, nx, nh; int row;
                if ((q & 1) == 0) { row = mt * 16 + gid;     ra = c0; za = c1; nx = v0; nh = v1; }
                else              { row = mt * 16 + gid + 8; ra = v2; za = v3; nx = c2; nh = c3; }
                float r = sigacc(ra), z = sigacc(za);
                float n = tanhacc(nx + r * nh);
                float hold = shh[row * GPAD + j];
                shh[row * GPAD + j] = tf32r((1.f - z) * n + z * hold);
            }
        asm volatile("bar.sync %0, 256;" :: "r"(bar));   // C

        size_t cbase = (size_t)node0 * 4096 + (size_t)t * 128;
        for (int i = htid; i < 1024; i += 256) {
            int nd = i >> 5, jq = i & 31;
            float4 v = *(const float4*)&shh[nd * GPAD + jq * 4];
            *(float4*)&g_ctx[cbase + (size_t)nd * 4096 + jq * 4] = v;
            if (t == 31) *(float4*)&g_h0[(size_t)(node0 + nd) * 128 + jq * 4] = v;
        }
    }
}

// ----------------- generic NT sgemm: C = act(A(M,K) @ B(Nc,K)^T) -----------------
__global__ void gemm_nt(const float* __restrict__ A, const float* __restrict__ B,
                        float* __restrict__ C, int M, int Nc, int K, int act) {
    __shared__ float As[16 * 68], Bs[16 * 68];
    int tid = threadIdx.x, n0 = blockIdx.x * 64, m0 = blockIdx.y * 64;
    int lrow = tid >> 2, kq = tid & 3, tx = tid & 15, ty = tid >> 4;
    float c[4][4];
#pragma unroll
    for (int i = 0; i < 4; i++)
#pragma unroll
        for (int jv = 0; jv < 4; jv++) c[i][jv] = 0.f;

    for (int k0 = 0; k0 < K; k0 += 16) {
        float4 av = *(const float4*)&A[(size_t)(m0 + lrow) * K + k0 + kq * 4];
        float4 bv = *(const float4*)&B[(size_t)(n0 + lrow) * K + k0 + kq * 4];
        __syncthreads();
        As[(kq*4+0)*68+lrow] = av.x; As[(kq*4+1)*68+lrow] = av.y;
        As[(kq*4+2)*68+lrow] = av.z; As[(kq*4+3)*68+lrow] = av.w;
        Bs[(kq*4+0)*68+lrow] = bv.x; Bs[(kq*4+1)*68+lrow] = bv.y;
        Bs[(kq*4+2)*68+lrow] = bv.z; Bs[(kq*4+3)*68+lrow] = bv.w;
        __syncthreads();
#pragma unroll
        for (int kk = 0; kk < 16; kk++) {
            float4 a = *(const float4*)&As[kk * 68 + ty * 4];
            float4 b = *(const float4*)&Bs[kk * 68 + tx * 4];
            float ar[4] = {a.x, a.y, a.z, a.w}, br[4] = {b.x, b.y, b.z, b.w};
#pragma unroll
            for (int i = 0; i < 4; i++)
#pragma unroll
                for (int jv = 0; jv < 4; jv++) c[i][jv] += ar[i] * br[jv];
        }
    }
#pragma unroll
    for (int i = 0; i < 4; i++)
#pragma unroll
        for (int jv = 0; jv < 4; jv++) {
            float v = c[i][jv];
            if (act == 1) v = tanhf(v);
            C[(size_t)(m0 + ty * 4 + i) * Nc + n0 + tx * 4 + jv] = v;
        }
}

// ----------------- temporal attention middle -----------------
__global__ void attn_mid(const float* __restrict__ ae, const float* __restrict__ ab) {
    __shared__ float sctx[32 * 129], sq[128], sw[32], sbt[32];
    int n = blockIdx.x, tid = threadIdx.x;
    sq[tid] = g_q[n * HH + tid];
    for (int idx = tid; idx < TT * HH; idx += 128) {
        int t = idx >> 7, k = idx & 127;
        sctx[t * 129 + k] = g_ctx[(size_t)n * (TT * HH) + idx];
    }
    __syncthreads();
    if (tid < 32) {
        float s = 0.f;
        for (int k = 0; k < 128; k++) s += sq[k] * sctx[tid * 129 + k];
        float m = s;
#pragma unroll
        for (int o = 16; o; o >>= 1) m = fmaxf(m, __shfl_xor_sync(0xffffffffu, m, o));
        float e = expf(s - m), su = e;
#pragma unroll
        for (int o = 16; o; o >>= 1) su += __shfl_xor_sync(0xffffffffu, su, o);
        sw[tid] = e / su;
        sbt[tid] = expf(-ab[n] * (float)(31 - tid));
    }
    __syncthreads();
    float aen = ae[n], acc = 0.f;
#pragma unroll 4
    for (int t = 0; t < TT; t++) {
        float mx = sw[t] * sctx[t * 129 + tid];
        acc += mx + fmaxf(aen * mx * sbt[t], 0.f);
    }
    g_comb[n * 256 + tid] = acc;
    g_comb[n * 256 + 128 + tid] = sq[tid];
}

// ----------------- CSR build (by src) -----------------
__global__ void count_src(const int* __restrict__ e0, int* cnt) {
    int i = blockIdx.x * blockDim.x + threadIdx.x;
    if (i < NZ) atomicAdd(&cnt[e0[i]], 1);
}
__global__ void scan_csr(const int* __restrict__ cnt, int* rowptr, float* Dinv, int* cursor) {
    __shared__ int s[1024];
    int tid = threadIdx.x, base = tid * 8, loc[8], sum = 0;
#pragma unroll
    for (int j = 0; j < 8; j++) { loc[j] = sum; sum += cnt[base + j]; }
    s[tid] = sum;
    __syncthreads();
    for (int off = 1; off < 1024; off <<= 1) {
        int v = (tid >= off) ? s[tid - off] : 0;
        __syncthreads();
        s[tid] += v;
        __syncthreads();
    }
    int excl = tid ? s[tid - 1] : 0;
#pragma unroll
    for (int j = 0; j < 8; j++) {
        rowptr[base + j] = excl + loc[j];
        int c = cnt[base + j];
        Dinv[base + j] = c ? 1.f / (float)c : 0.f;
        cursor[base + j] = 0;
    }
    if (tid == 1023) rowptr[NN] = s[1023];
}
__global__ void fill_csr(const int* __restrict__ e0, const int* __restrict__ rowptr,
                         int* cursor, int* adj, unsigned* segmax, float* segsum) {
    int i = blockIdx.x * blockDim.x + threadIdx.x;
    if (i >= NZ) return;
    if (i < NN * NHEADS) { segmax[i] = 0u; segsum[i] = 0.f; }
    int sg = e0[i];
    int p = atomicAdd(&cursor[sg], 1);
    adj[rowptr[sg] + p] = i;
}

// ----------------- hypergraph pieces -----------------
__global__ void efeat(const int* __restrict__ e0, const float* __restrict__ x, float* ef,
                      unsigned* segmax, float* segsum, int zeroseg) {
    int d = blockIdx.x, c = threadIdx.x;
    if (zeroseg) {
        int gid = d * 128 + c;
        if (gid < NN) { segmax[gid] = 0u; segsum[gid] = 0.f; }
    }
    float a = 0.f;
#pragma unroll 4
    for (int j = 0; j < 32; j++) a += x[e0[d + j * EE] * HH + c];
    ef[d * HH + c] = a;
}

__global__ void rowdot(const float* __restrict__ xw, const float* __restrict__ att,
                       int stride, int heads, float* __restrict__ out) {
    int r = blockIdx.x, h = threadIdx.x >> 5, lane = threadIdx.x & 31;
    const float* row = xw + (size_t)(r * heads + h) * HH;
    float s = 0.f;
#pragma unroll
    for (int m = 0; m < 4; m++) s += row[lane + 32 * m] * att[h * stride + lane + 32 * m];
#pragma unroll
    for (int o = 16; o; o >>= 1) s += __shfl_xor_sync(0xffffffffu, s, o);
    if (!lane) out[r * heads + h] = s;
}

__global__ void alpha_max(const int* __restrict__ e0, const int* __restrict__ e1,
                          const float* __restrict__ xa, const float* __restrict__ ea,
                          int heads) {
    int g = blockIdx.x * blockDim.x + threadIdx.x;
    if (g >= NZ * heads) return;
    int i = g / heads, h = g - i * heads;
    float a = xa[e0[i] * heads + h] + ea[e1[i] * heads + h];
    a = (a > 0.f) ? a : 0.2f * a;
    g_alpha[g] = a;
    atomicMax(&g_segmax[e0[i] * heads + h], fenc(a));
}
__global__ void alpha_exp(const int* __restrict__ e0, int heads) {
    int g = blockIdx.x * blockDim.x + threadIdx.x;
    if (g >= NZ * heads) return;
    int i = g / heads, h = g - i * heads;
    float ex = expf(g_alpha[g] - fdec(g_segmax[e0[i] * heads + h]));
    g_alpha[g] = ex;
    atomicAdd(&g_segsum[e0[i] * heads + h], ex);
}

template <int HT>
__global__ void eout_gather(const int* __restrict__ e0, const float* __restrict__ xw) {
    int d = blockIdx.x, c = threadIdx.x;
    float acc[HT];
#pragma unroll
    for (int h = 0; h < HT; h++) acc[h] = 0.f;
    for (int j = 0; j < 32; j++) {
        int i = d + j * EE, s = e0[i];
#pragma unroll
        for (int h = 0; h < HT; h++) {
            float an = g_alpha[i * HT + h] / (g_segsum[s * HT + h] + 1e-16f);
            acc[h] += an * xw[(size_t)(s * HT + h) * HH + c];
        }
    }
#pragma unroll
    for (int h = 0; h < HT; h++)
        g_eout[(size_t)(d * HT + h) * HH + c] = acc[h] * (1.f / 32.f);
}

template <int HT>
__global__ void node_out(const int* __restrict__ e1, const float* __restrict__ bias,
                         float* __restrict__ out) {
    int s = blockIdx.x, c = threadIdx.x;
    int b = g_rowptr[s], e = g_rowptr[s + 1];
    float ssv[HT];
#pragma unroll
    for (int h = 0; h < HT; h++) ssv[h] = g_segsum[s * HT + h] + 1e-16f;
    float a[HT];
#pragma unroll
    for (int h = 0; h < HT; h++) a[h] = 0.f;
    for (int k = b; k < e; k++) {
        int i = g_adj[k], d = e1[i];
#pragma unroll
        for (int h = 0; h < HT; h++)
            a[h] += (g_alpha[i * HT + h] / ssv[h]) * g_eout[(size_t)(d * HT + h) * HH + c];
    }
    float v = 0.f;
#pragma unroll
    for (int h = 0; h < HT; h++) v += a[h];
    v = v * g_Dinv[s] * (1.f / HT) + bias[c];
    out[s * HH + c] = (v > 0.f) ? v : 0.2f * v;
}

__global__ void head_k(const float* __restrict__ x2, const float* __restrict__ Wo,
                       const float* __restrict__ bo, float* __restrict__ out) {
    int n = blockIdx.x * 4 + (threadIdx.x >> 5), lane = threadIdx.x & 31;
    float s = 0.f;
#pragma unroll
    for (int m = 0; m < 4; m++) s += x2[n * HH + lane + 32 * m] * Wo[lane + 32 * m];
#pragma unroll
    for (int o = 16; o; o >>= 1) s += __shfl_xor_sync(0xffffffffu, s, o);
    if (!lane) {
        float v = s + bo[0];
        out[n] = (v > 0.f) ? v : 0.01f * v;
    }
}

// ----------------- host -----------------
static void* sym(const void* s) { void* p = 0; cudaGetSymbolAddress(&p, s); return p; }

extern "C" void kernel_launch(void* const* d_in, const int* in_sizes, int n_in,
                              void* d_out, int out_size) {
    const float* price = (const float*)d_in[0];
    const int*   e     = (const int*)d_in[1];
    const float* bn1g  = (const float*)d_in[2];
    const float* bn1b  = (const float*)d_in[3];
    const float* Wih   = (const float*)d_in[4];
    const float* Whh   = (const float*)d_in[5];
    const float* bih   = (const float*)d_in[6];
    const float* bhh   = (const float*)d_in[7];
    const float* Wq    = (const float*)d_in[8];
    const float* Wout  = (const float*)d_in[9];
    const float* ae    = (const float*)d_in[10];
    const float* ab    = (const float*)d_in[11];
    const float* bn2g  = (const float*)d_in[12];
    const float* bn2b  = (const float*)d_in[13];
    const float* W1    = (const float*)d_in[14];
    const float* att1  = (const float*)d_in[15];
    const float* bias1 = (const float*)d_in[16];
    const float* W2    = (const float*)d_in[17];
    const float* att2  = (const float*)d_in[18];
    const float* bias2 = (const float*)d_in[19];
    const float* Wo    = (const float*)d_in[20];
    const float* bo    = (const float*)d_in[21];
    const int* e0 = e;
    const int* e1 = e + NZ;

    float* out_nf = (float*)d_out;
    float* out_x  = out_nf + NH;
    float* out_o  = out_x + NH;

    float* p_sum1 = (float*)sym(g_sum1);   float* p_sq1 = (float*)sym(g_sq1);
    float* p_sum2 = (float*)sym(g_sum2);   float* p_sq2 = (float*)sym(g_sq2);
    float* p_sc1 = (float*)sym(g_scale1);  float* p_sh1 = (float*)sym(g_shift1);
    float* p_sc2 = (float*)sym(g_scale2);  float* p_sh2 = (float*)sym(g_shift2);
    float* p_h0 = (float*)sym(g_h0);
    float* p_q = (float*)sym(g_q);         float* p_comb = (float*)sym(g_comb);
    float* p_xbn = (float*)sym(g_xbn);     float* p_ef = (float*)sym(g_ef);
    float* p_xw = (float*)sym(g_xw);       float* p_ew = (float*)sym(g_ew);
    float* p_xa = (float*)sym(g_xa);       float* p_ea = (float*)sym(g_ea);
    unsigned* p_smax = (unsigned*)sym(g_segmax);
    float* p_ssum = (float*)sym(g_segsum);
    float* p_x1 = (float*)sym(g_x1);
    int* p_cnt = (int*)sym(g_cnt);         int* p_cur = (int*)sym(g_cursor);
    int* p_rp = (int*)sym(g_rowptr);       int* p_adj = (int*)sym(g_adj);
    float* p_Dinv = (float*)sym(g_Dinv);

    // launches 1-3, so launch #4 (ncu capture slot) = gru_persist
    bn_stats<<<16, 1024>>>(price, 512, p_sum1, p_sq1);
    bn_finalize<<<4, 128>>>(p_sum1, p_sq1, bn1g, bn1b, p_sc1, p_sh1, 512);
    prep_all<<<704, 256>>>(Whh, Wih, bih, bhh);

    gru_persist<<<128, 512>>>(price);   // full 32-step GRU, hT -> g_h0, ctx -> g_ctx

    gemm_nt<<<dim3(2, NN / 64), 256>>>(p_h0, Wq, p_q, NN, 128, 128, 0);
    attn_mid<<<NN, 128>>>(ae, ab);
    gemm_nt<<<dim3(2, NN / 64), 256>>>(p_comb, Wout, out_nf, NN, 128, 256, 1);

    bn_stats<<<4, 1024>>>(out_nf, 128, p_sum2, p_sq2);
    bn_finalize<<<1, 128>>>(p_sum2, p_sq2, bn2g, bn2b, p_sc2, p_sh2, 128);
    bn_apply<<<NH / 256, 256>>>(out_nf, p_sc2, p_sh2, p_xbn, p_cnt);

    // CSR by src
    count_src<<<NZ / 256, 256>>>(e0, p_cnt);
    scan_csr<<<1, 1024>>>(p_cnt, p_rp, p_Dinv, p_cur);
    fill_csr<<<NZ / 256, 256>>>(e0, p_rp, p_cur, p_adj, p_smax, p_ssum);

    // ---- conv 1 (4 heads) ----
    efeat<<<EE, 128>>>(e0, p_xbn, p_ef, p_smax, p_ssum, 0);
    gemm_nt<<<dim3(8, NN / 64), 256>>>(p_xbn, W1, p_xw, NN, 512, 128, 0);
    gemm_nt<<<dim3(8, EE / 64), 256>>>(p_ef, W1, p_ew, EE, 512, 128, 0);
    rowdot<<<NN, 128>>>(p_xw, att1, 256, NHEADS, p_xa);
    rowdot<<<EE, 128>>>(p_ew, att1 + 128, 256, NHEADS, p_ea);
    alpha_max<<<NZ * NHEADS / 256, 256>>>(e0, e1, p_xa, p_ea, NHEADS);
    alpha_exp<<<NZ * NHEADS / 256, 256>>>(e0, NHEADS);
    eout_gather<NHEADS><<<EE, 128>>>(e0, p_xw);
    node_out<NHEADS><<<NN, 128>>>(e1, bias1, p_x1);

    // ---- conv 2 (1 head) ----
    efeat<<<EE, 128>>>(e0, p_x1, p_ef, p_smax, p_ssum, 1);
    gemm_nt<<<dim3(2, NN / 64), 256>>>(p_x1, W2, p_xw, NN, 128, 128, 0);
    gemm_nt<<<dim3(2, EE / 64), 256>>>(p_ef, W2, p_ew, EE, 128, 128, 0);
    rowdot<<<NN, 32>>>(p_xw, att2, 256, 1, p_xa);
    rowdot<<<EE, 32>>>(p_ew, att2 + 128, 256, 1, p_ea);
    alpha_max<<<NZ / 256, 256>>>(e0, e1, p_xa, p_ea, 1);
    alpha_exp<<<NZ / 256, 256>>>(e0, 1);
    eout_gather<1><<<EE, 128>>>(e0, p_xw);
    node_out<1><<<NN, 128>>>(e1, bias2, out_x);

    head_k<<<NN / 4, 128>>>(out_x, Wo, bo, out_o);
}